// round 1
// baseline (speedup 1.0000x reference)
#include <cuda_runtime.h>
#include <cuda_bf16.h>

// Problem constants
#define Bb 4
#define Tt 4096
#define Cc 1024
#define Hh 64

// Scratch for projected q/k/v (4 MB each)
__device__ float g_q[Bb * Tt * Hh];
__device__ float g_k[Bb * Tt * Hh];
__device__ float g_v[Bb * Tt * Hh];

__device__ __forceinline__ void fma4(float4& d, float s, const float4 v) {
    d.x += s * v.x; d.y += s * v.y; d.z += s * v.z; d.w += s * v.w;
}
__device__ __forceinline__ void scale4(float4& d, float s) {
    d.x *= s; d.y *= s; d.z *= s; d.w *= s;
}

// ---------------------------------------------------------------------------
// Kernel 1: QKV projection.  out[m][h] = sum_c x[m][c] * w[c][h]
// M = B*T = 16384, K = 1024, N = 64.  BM=64, BK=32, N=64 in one tile.
// 256 threads (16x16), 4x4 thread tile, float4 dot4 inner loop.
// blockIdx.y selects weight: 0->k, 1->q (scaled by 1/8), 2->v
// ---------------------------------------------------------------------------
__global__ __launch_bounds__(256) void proj_kernel(
    const float* __restrict__ x,
    const float* __restrict__ wk,
    const float* __restrict__ wq,
    const float* __restrict__ wv)
{
    __shared__ float Xs[64 * 32];
    __shared__ float Ws[32 * 64];

    const int z = blockIdx.y;
    const float* __restrict__ w = (z == 0) ? wk : ((z == 1) ? wq : wv);
    float* __restrict__ outp = (z == 0) ? g_k : ((z == 1) ? g_q : g_v);
    const float scale = (z == 1) ? 0.125f : 1.0f;   // 1/sqrt(H) folded into q

    const int m0 = blockIdx.x * 64;
    const int tid = threadIdx.x;
    const int tx = tid & 15;
    const int ty = tid >> 4;

    float4 acc[4];
    #pragma unroll
    for (int i = 0; i < 4; i++) acc[i] = make_float4(0.f, 0.f, 0.f, 0.f);

    for (int k0 = 0; k0 < Cc; k0 += 32) {
        // Load X tile 64x32 (float4 coalesced)
        {
            const int c = tid & 7;          // 8 float4 cols
            const int r = tid >> 3;         // 32 rows
            #pragma unroll
            for (int it = 0; it < 2; it++) {
                const int rr = r + it * 32;
                *(float4*)&Xs[rr * 32 + c * 4] =
                    *(const float4*)&x[(size_t)(m0 + rr) * Cc + k0 + c * 4];
            }
        }
        // Load W tile 32x64
        {
            const int c = tid & 15;         // 16 float4 cols
            const int r = tid >> 4;         // 16 rows per pass
            #pragma unroll
            for (int it = 0; it < 2; it++) {
                const int rr = r + it * 16;
                *(float4*)&Ws[rr * 64 + c * 4] =
                    *(const float4*)&w[(size_t)(k0 + rr) * Hh + c * 4];
            }
        }
        __syncthreads();

        #pragma unroll
        for (int kk = 0; kk < 8; kk++) {
            float4 a0 = *(const float4*)&Xs[(ty * 4 + 0) * 32 + kk * 4];
            float4 a1 = *(const float4*)&Xs[(ty * 4 + 1) * 32 + kk * 4];
            float4 a2 = *(const float4*)&Xs[(ty * 4 + 2) * 32 + kk * 4];
            float4 a3 = *(const float4*)&Xs[(ty * 4 + 3) * 32 + kk * 4];
            float4 b0 = *(const float4*)&Ws[(kk * 4 + 0) * 64 + tx * 4];
            float4 b1 = *(const float4*)&Ws[(kk * 4 + 1) * 64 + tx * 4];
            float4 b2 = *(const float4*)&Ws[(kk * 4 + 2) * 64 + tx * 4];
            float4 b3 = *(const float4*)&Ws[(kk * 4 + 3) * 64 + tx * 4];
            fma4(acc[0], a0.x, b0); fma4(acc[0], a0.y, b1); fma4(acc[0], a0.z, b2); fma4(acc[0], a0.w, b3);
            fma4(acc[1], a1.x, b0); fma4(acc[1], a1.y, b1); fma4(acc[1], a1.z, b2); fma4(acc[1], a1.w, b3);
            fma4(acc[2], a2.x, b0); fma4(acc[2], a2.y, b1); fma4(acc[2], a2.z, b2); fma4(acc[2], a2.w, b3);
            fma4(acc[3], a3.x, b0); fma4(acc[3], a3.y, b1); fma4(acc[3], a3.z, b2); fma4(acc[3], a3.w, b3);
        }
        __syncthreads();
    }

    #pragma unroll
    for (int i = 0; i < 4; i++) {
        scale4(acc[i], scale);
        *(float4*)&outp[(size_t)(m0 + ty * 4 + i) * Hh + tx * 4] = acc[i];
    }
}

// ---------------------------------------------------------------------------
// Kernel 2: causal flash attention with additive bias.
// Grid: (T/64, B).  CTA = one 64-row q tile; iterates k tiles 0..qt (causal).
// 256 threads (16x16); S tile thread-layout (q=ty*4+i, k=tx*4+j);
// O accumulator thread-layout (q=ty*4+i, h=tx*4+j).
// K tile stored with XOR-swizzled float4 columns so QK^T B-reads are
// conflict-free; P staged through smem for the PV GEMM.
// ---------------------------------------------------------------------------
__global__ __launch_bounds__(256) void attn_kernel(
    const float* __restrict__ bias,
    float* __restrict__ outp)
{
    extern __shared__ float smf[];
    float* Qs = smf;              // 64x64 row-major [q][h]
    float* Ks = smf + 4096;       // 64x64 [k][h], float4-col swizzled by (k>>2)
    float* Vs = smf + 8192;       // 64x64 row-major [k][h]
    float* Ps = smf + 12288;      // 64x64 row-major [q][k]

    const int b  = blockIdx.y;
    const int qt = (gridDim.x - 1) - blockIdx.x;   // longest tiles first
    const int q0 = qt * 64;
    const int tid = threadIdx.x;
    const int tx = tid & 15;
    const int ty = tid >> 4;

    const float* __restrict__ qbase = g_q + (size_t)b * Tt * Hh;
    const float* __restrict__ kbase = g_k + (size_t)b * Tt * Hh;
    const float* __restrict__ vbase = g_v + (size_t)b * Tt * Hh;

    // Load Q tile
    {
        const int c = tid & 15, r = tid >> 4;
        #pragma unroll
        for (int it = 0; it < 4; it++) {
            const int rr = r + it * 16;
            *(float4*)&Qs[rr * 64 + c * 4] =
                *(const float4*)&qbase[(size_t)(q0 + rr) * Hh + c * 4];
        }
    }

    float4 acc[4];
    float mrow[4], lrow[4];
    #pragma unroll
    for (int i = 0; i < 4; i++) {
        acc[i] = make_float4(0.f, 0.f, 0.f, 0.f);
        mrow[i] = -1e30f;
        lrow[i] = 0.f;
    }

    const int ntiles = qt + 1;
    for (int t = 0; t < ntiles; t++) {
        const int k0 = t * 64;

        // Load K (swizzled) and V tiles
        {
            const int c = tid & 15, r = tid >> 4;
            #pragma unroll
            for (int it = 0; it < 4; it++) {
                const int rr = r + it * 16;
                const int pc = c ^ (rr >> 2);
                float4 kv = *(const float4*)&kbase[(size_t)(k0 + rr) * Hh + c * 4];
                float4 vv = *(const float4*)&vbase[(size_t)(k0 + rr) * Hh + c * 4];
                *(float4*)&Ks[rr * 64 + pc * 4] = kv;
                *(float4*)&Vs[rr * 64 + c * 4] = vv;
            }
        }
        __syncthreads();

        // --- S = Q K^T  (dot4 over h) ---
        float4 sv[4];
        #pragma unroll
        for (int i = 0; i < 4; i++) sv[i] = make_float4(0.f, 0.f, 0.f, 0.f);

        #pragma unroll
        for (int hh = 0; hh < 16; hh++) {
            float4 a0 = *(const float4*)&Qs[(ty * 4 + 0) * 64 + hh * 4];
            float4 a1 = *(const float4*)&Qs[(ty * 4 + 1) * 64 + hh * 4];
            float4 a2 = *(const float4*)&Qs[(ty * 4 + 2) * 64 + hh * 4];
            float4 a3 = *(const float4*)&Qs[(ty * 4 + 3) * 64 + hh * 4];
            const int pc = (hh ^ tx) * 4;  // (kj>>2)==tx for kj=4tx+j
            float4 b0 = *(const float4*)&Ks[(tx * 4 + 0) * 64 + pc];
            float4 b1 = *(const float4*)&Ks[(tx * 4 + 1) * 64 + pc];
            float4 b2 = *(const float4*)&Ks[(tx * 4 + 2) * 64 + pc];
            float4 b3 = *(const float4*)&Ks[(tx * 4 + 3) * 64 + pc];
            #define QKDOT(S, A) \
                S.x += A.x*b0.x + A.y*b0.y + A.z*b0.z + A.w*b0.w; \
                S.y += A.x*b1.x + A.y*b1.y + A.z*b1.z + A.w*b1.w; \
                S.z += A.x*b2.x + A.y*b2.y + A.z*b2.z + A.w*b2.w; \
                S.w += A.x*b3.x + A.y*b3.y + A.z*b3.z + A.w*b3.w;
            QKDOT(sv[0], a0) QKDOT(sv[1], a1) QKDOT(sv[2], a2) QKDOT(sv[3], a3)
            #undef QKDOT
        }

        // --- bias + causal mask ---
        const bool diag = (k0 == q0);
        #pragma unroll
        for (int i = 0; i < 4; i++) {
            const int qg = q0 + ty * 4 + i;
            float4 bz = *(const float4*)&bias[(size_t)qg * Tt + k0 + tx * 4];
            sv[i].x += bz.x; sv[i].y += bz.y; sv[i].z += bz.z; sv[i].w += bz.w;
            if (diag) {
                const int kg = k0 + tx * 4;
                if (kg + 0 > qg) sv[i].x = -1e30f;
                if (kg + 1 > qg) sv[i].y = -1e30f;
                if (kg + 2 > qg) sv[i].z = -1e30f;
                if (kg + 3 > qg) sv[i].w = -1e30f;
            }
        }

        // --- online softmax (row reduce over 16 tx lanes, same warp half) ---
        #pragma unroll
        for (int i = 0; i < 4; i++) {
            float mx = fmaxf(fmaxf(sv[i].x, sv[i].y), fmaxf(sv[i].z, sv[i].w));
            #pragma unroll
            for (int o = 1; o < 16; o <<= 1)
                mx = fmaxf(mx, __shfl_xor_sync(0xffffffffu, mx, o, 32));
            const float mnew = fmaxf(mrow[i], mx);
            const float corr = __expf(mrow[i] - mnew);
            mrow[i] = mnew;
            sv[i].x = __expf(sv[i].x - mnew);
            sv[i].y = __expf(sv[i].y - mnew);
            sv[i].z = __expf(sv[i].z - mnew);
            sv[i].w = __expf(sv[i].w - mnew);
            float rs = sv[i].x + sv[i].y + sv[i].z + sv[i].w;
            #pragma unroll
            for (int o = 1; o < 16; o <<= 1)
                rs += __shfl_xor_sync(0xffffffffu, rs, o, 32);
            lrow[i] = lrow[i] * corr + rs;
            scale4(acc[i], corr);
            *(float4*)&Ps[(ty * 4 + i) * 64 + tx * 4] = sv[i];
        }
        __syncthreads();

        // --- O += P V  (inner over k, float4 groups of 4) ---
        #pragma unroll
        for (int kk = 0; kk < 16; kk++) {
            float4 a0 = *(const float4*)&Ps[(ty * 4 + 0) * 64 + kk * 4];
            float4 a1 = *(const float4*)&Ps[(ty * 4 + 1) * 64 + kk * 4];
            float4 a2 = *(const float4*)&Ps[(ty * 4 + 2) * 64 + kk * 4];
            float4 a3 = *(const float4*)&Ps[(ty * 4 + 3) * 64 + kk * 4];
            float4 b0 = *(const float4*)&Vs[(kk * 4 + 0) * 64 + tx * 4];
            float4 b1 = *(const float4*)&Vs[(kk * 4 + 1) * 64 + tx * 4];
            float4 b2 = *(const float4*)&Vs[(kk * 4 + 2) * 64 + tx * 4];
            float4 b3 = *(const float4*)&Vs[(kk * 4 + 3) * 64 + tx * 4];
            fma4(acc[0], a0.x, b0); fma4(acc[0], a0.y, b1); fma4(acc[0], a0.z, b2); fma4(acc[0], a0.w, b3);
            fma4(acc[1], a1.x, b0); fma4(acc[1], a1.y, b1); fma4(acc[1], a1.z, b2); fma4(acc[1], a1.w, b3);
            fma4(acc[2], a2.x, b0); fma4(acc[2], a2.y, b1); fma4(acc[2], a2.z, b2); fma4(acc[2], a2.w, b3);
            fma4(acc[3], a3.x, b0); fma4(acc[3], a3.y, b1); fma4(acc[3], a3.z, b2); fma4(acc[3], a3.w, b3);
        }
        __syncthreads();
    }

    // --- final normalize + write ---
    #pragma unroll
    for (int i = 0; i < 4; i++) {
        const float inv = 1.0f / lrow[i];
        scale4(acc[i], inv);
        *(float4*)&outp[((size_t)b * Tt + q0 + ty * 4 + i) * Hh + tx * 4] = acc[i];
    }
}

// ---------------------------------------------------------------------------
extern "C" void kernel_launch(void* const* d_in, const int* in_sizes, int n_in,
                              void* d_out, int out_size)
{
    const float* x    = (const float*)d_in[0];
    const float* bias = (const float*)d_in[1];
    const float* wk   = (const float*)d_in[2];
    const float* wq   = (const float*)d_in[3];
    const float* wv   = (const float*)d_in[4];
    float* out = (float*)d_out;

    // QKV projection: 256 M-tiles x 3 weights
    dim3 g1(256, 3);
    proj_kernel<<<g1, 256>>>(x, wk, wq, wv);

    // Flash attention: 64 q-tiles x 4 batches, 64 KB dynamic smem
    cudaFuncSetAttribute(attn_kernel,
                         cudaFuncAttributeMaxDynamicSharedMemorySize, 65536);
    dim3 g2(Tt / 64, Bb);
    attn_kernel<<<g2, 256, 65536>>>(bias, out);
}

// round 2
// speedup vs baseline: 1.7244x; 1.7244x over previous
#include <cuda_runtime.h>
#include <cuda_bf16.h>
#include <cstdint>

// Problem constants
#define Bb 4
#define Tt 4096
#define Cc 1024
#define Hh 64
#define PAD 68   // smem row stride (floats) -> conflict-free tf32 fragment LDS

// Scratch for projected q/k/v (4 MB each)
__device__ float g_q[Bb * Tt * Hh];
__device__ float g_k[Bb * Tt * Hh];
__device__ float g_v[Bb * Tt * Hh];

__device__ __forceinline__ uint32_t f2tf(float f) {
    uint32_t u; asm("cvt.rna.tf32.f32 %0, %1;" : "=r"(u) : "f"(f)); return u;
}

// D += A(16x8) * B(8x8)^T-ish (row.col), tf32 in, f32 accum
__device__ __forceinline__ void mma_tf32(float* d, const uint32_t* a,
                                         uint32_t b0, uint32_t b1) {
    asm volatile(
        "mma.sync.aligned.m16n8k8.row.col.f32.tf32.tf32.f32 "
        "{%0,%1,%2,%3}, {%4,%5,%6,%7}, {%8,%9}, {%0,%1,%2,%3};"
        : "+f"(d[0]), "+f"(d[1]), "+f"(d[2]), "+f"(d[3])
        : "r"(a[0]), "r"(a[1]), "r"(a[2]), "r"(a[3]), "r"(b0), "r"(b1));
}

// ---------------------------------------------------------------------------
// Kernel 1: QKV projection via tf32 mma.  out[m][h] = sum_c x[m][c] * w[c][h]
// M=16384, K=1024, N=64.  CTA: 128 threads (4 warps), 64-row M tile.
// Each warp: m16 x n64 (8 n-tiles) x K, k-chunks of 64.
// blockIdx.y: 0->k, 1->q (x0.125), 2->v
// ---------------------------------------------------------------------------
__global__ __launch_bounds__(128) void proj_kernel(
    const float* __restrict__ x,
    const float* __restrict__ wk,
    const float* __restrict__ wq,
    const float* __restrict__ wv)
{
    __shared__ uint32_t Xs[64 * PAD];   // [m][c] tf32
    __shared__ uint32_t Ws[64 * PAD];   // [c][h] tf32

    const int z = blockIdx.y;
    const float* __restrict__ w = (z == 0) ? wk : ((z == 1) ? wq : wv);
    float* __restrict__ outp = (z == 0) ? g_k : ((z == 1) ? g_q : g_v);
    const float scale = (z == 1) ? 0.125f : 1.0f;

    const int m0 = blockIdx.x * 64;
    const int tid = threadIdx.x;
    const int wid = tid >> 5;
    const int lane = tid & 31;
    const int gid = lane >> 2;      // group id (row within fragment)
    const int tig = lane & 3;       // thread in group

    float o[8][4];
    #pragma unroll
    for (int nt = 0; nt < 8; nt++)
        #pragma unroll
        for (int j = 0; j < 4; j++) o[nt][j] = 0.f;

    const int lc = tid & 15;        // float4 column
    const int lr = tid >> 4;        // row base (8 rows per pass)

    for (int k0 = 0; k0 < Cc; k0 += 64) {
        #pragma unroll
        for (int p = 0; p < 8; p++) {
            const int row = p * 8 + lr;
            float4 xv = *(const float4*)&x[(size_t)(m0 + row) * Cc + k0 + lc * 4];
            float4 wv4 = *(const float4*)&w[(size_t)(k0 + row) * Hh + lc * 4];
            uint32_t* xd = &Xs[row * PAD + lc * 4];
            xd[0] = f2tf(xv.x); xd[1] = f2tf(xv.y); xd[2] = f2tf(xv.z); xd[3] = f2tf(xv.w);
            uint32_t* wd = &Ws[row * PAD + lc * 4];
            wd[0] = f2tf(wv4.x); wd[1] = f2tf(wv4.y); wd[2] = f2tf(wv4.z); wd[3] = f2tf(wv4.w);
        }
        __syncthreads();

        #pragma unroll
        for (int s8 = 0; s8 < 8; s8++) {
            uint32_t a[4];
            const int ar = wid * 16 + gid;
            a[0] = Xs[(ar    ) * PAD + s8 * 8 + tig    ];
            a[1] = Xs[(ar + 8) * PAD + s8 * 8 + tig    ];
            a[2] = Xs[(ar    ) * PAD + s8 * 8 + tig + 4];
            a[3] = Xs[(ar + 8) * PAD + s8 * 8 + tig + 4];
            #pragma unroll
            for (int nt = 0; nt < 8; nt++) {
                uint32_t b0 = Ws[(s8 * 8 + tig    ) * PAD + nt * 8 + gid];
                uint32_t b1 = Ws[(s8 * 8 + tig + 4) * PAD + nt * 8 + gid];
                mma_tf32(o[nt], a, b0, b1);
            }
        }
        __syncthreads();
    }

    const int mr = m0 + wid * 16 + gid;
    #pragma unroll
    for (int nt = 0; nt < 8; nt++) {
        float2 lo = make_float2(o[nt][0] * scale, o[nt][1] * scale);
        float2 hi = make_float2(o[nt][2] * scale, o[nt][3] * scale);
        *(float2*)&outp[(size_t)(mr    ) * Hh + nt * 8 + tig * 2] = lo;
        *(float2*)&outp[(size_t)(mr + 8) * Hh + nt * 8 + tig * 2] = hi;
    }
}

// ---------------------------------------------------------------------------
// Kernel 2: causal flash attention, tf32 mma for QK^T and PV.
// Grid (T/64, B), CTA = 128 threads (4 warps), BQ=64 (16 q-rows/warp), BK=64.
// Q fragments register-resident; K/V/P staged in padded smem.
// ---------------------------------------------------------------------------
__global__ __launch_bounds__(128) void attn_kernel(
    const float* __restrict__ bias,
    float* __restrict__ outp)
{
    extern __shared__ uint32_t smu[];
    uint32_t* Ks = smu;                 // [key][h] tf32, stride PAD
    uint32_t* Vs = smu + 64 * PAD;      // [key][h] tf32, stride PAD
    uint32_t* Ps = smu + 128 * PAD;     // [q][key] tf32, stride PAD

    const int b  = blockIdx.y;
    const int qt = (gridDim.x - 1) - blockIdx.x;   // longest q-tiles first
    const int q0 = qt * 64;
    const int tid = threadIdx.x;
    const int wid = tid >> 5;
    const int lane = tid & 31;
    const int gid = lane >> 2;
    const int tig = lane & 3;

    const float* __restrict__ qbase = g_q + (size_t)b * Tt * Hh;
    const float* __restrict__ kbase = g_k + (size_t)b * Tt * Hh;
    const float* __restrict__ vbase = g_v + (size_t)b * Tt * Hh;

    // Q fragments for this warp's 16 rows, all of H=64 (8 k-steps), in regs.
    const int qr0 = q0 + wid * 16 + gid;   // fragment row (low)
    uint32_t qa[8][4];
    #pragma unroll
    for (int s8 = 0; s8 < 8; s8++) {
        qa[s8][0] = f2tf(qbase[(size_t)(qr0    ) * Hh + s8 * 8 + tig    ]);
        qa[s8][1] = f2tf(qbase[(size_t)(qr0 + 8) * Hh + s8 * 8 + tig    ]);
        qa[s8][2] = f2tf(qbase[(size_t)(qr0    ) * Hh + s8 * 8 + tig + 4]);
        qa[s8][3] = f2tf(qbase[(size_t)(qr0 + 8) * Hh + s8 * 8 + tig + 4]);
    }

    float o[8][4];
    #pragma unroll
    for (int nt = 0; nt < 8; nt++)
        #pragma unroll
        for (int j = 0; j < 4; j++) o[nt][j] = 0.f;
    float m0r = -1e30f, m1r = -1e30f, l0 = 0.f, l1 = 0.f;

    const int lc = tid & 15;
    const int lr = tid >> 4;

    for (int t = 0; t <= qt; t++) {
        const int k0 = t * 64;

        // Load K/V tile -> tf32 smem
        #pragma unroll
        for (int p = 0; p < 8; p++) {
            const int row = p * 8 + lr;
            float4 kv = *(const float4*)&kbase[(size_t)(k0 + row) * Hh + lc * 4];
            float4 vv = *(const float4*)&vbase[(size_t)(k0 + row) * Hh + lc * 4];
            uint32_t* kd = &Ks[row * PAD + lc * 4];
            kd[0] = f2tf(kv.x); kd[1] = f2tf(kv.y); kd[2] = f2tf(kv.z); kd[3] = f2tf(kv.w);
            uint32_t* vd = &Vs[row * PAD + lc * 4];
            vd[0] = f2tf(vv.x); vd[1] = f2tf(vv.y); vd[2] = f2tf(vv.z); vd[3] = f2tf(vv.w);
        }
        __syncthreads();

        // --- S = Q K^T ---  (contraction over h; n = key index)
        float s[8][4];
        #pragma unroll
        for (int nt = 0; nt < 8; nt++)
            #pragma unroll
            for (int j = 0; j < 4; j++) s[nt][j] = 0.f;

        #pragma unroll
        for (int s8 = 0; s8 < 8; s8++) {
            #pragma unroll
            for (int nt = 0; nt < 8; nt++) {
                uint32_t b0 = Ks[(nt * 8 + gid) * PAD + s8 * 8 + tig    ];
                uint32_t b1 = Ks[(nt * 8 + gid) * PAD + s8 * 8 + tig + 4];
                mma_tf32(s[nt], qa[s8], b0, b1);
            }
        }

        // --- bias + causal mask ---
        const bool diag = (t == qt);
        #pragma unroll
        for (int nt = 0; nt < 8; nt++) {
            const int c0 = k0 + nt * 8 + tig * 2;
            float2 bz0 = *(const float2*)&bias[(size_t)(qr0    ) * Tt + c0];
            float2 bz1 = *(const float2*)&bias[(size_t)(qr0 + 8) * Tt + c0];
            s[nt][0] += bz0.x; s[nt][1] += bz0.y;
            s[nt][2] += bz1.x; s[nt][3] += bz1.y;
            if (diag) {
                if (c0     > qr0    ) s[nt][0] = -1e30f;
                if (c0 + 1 > qr0    ) s[nt][1] = -1e30f;
                if (c0     > qr0 + 8) s[nt][2] = -1e30f;
                if (c0 + 1 > qr0 + 8) s[nt][3] = -1e30f;
            }
        }

        // --- online softmax (rows qr0 and qr0+8; 4 lanes per row) ---
        float mx0 = -1e30f, mx1 = -1e30f;
        #pragma unroll
        for (int nt = 0; nt < 8; nt++) {
            mx0 = fmaxf(mx0, fmaxf(s[nt][0], s[nt][1]));
            mx1 = fmaxf(mx1, fmaxf(s[nt][2], s[nt][3]));
        }
        mx0 = fmaxf(mx0, __shfl_xor_sync(0xffffffffu, mx0, 1));
        mx0 = fmaxf(mx0, __shfl_xor_sync(0xffffffffu, mx0, 2));
        mx1 = fmaxf(mx1, __shfl_xor_sync(0xffffffffu, mx1, 1));
        mx1 = fmaxf(mx1, __shfl_xor_sync(0xffffffffu, mx1, 2));

        const float mn0 = fmaxf(m0r, mx0);
        const float mn1 = fmaxf(m1r, mx1);
        const float cr0 = __expf(m0r - mn0);
        const float cr1 = __expf(m1r - mn1);
        m0r = mn0; m1r = mn1;

        float rs0 = 0.f, rs1 = 0.f;
        #pragma unroll
        for (int nt = 0; nt < 8; nt++) {
            s[nt][0] = __expf(s[nt][0] - mn0);
            s[nt][1] = __expf(s[nt][1] - mn0);
            s[nt][2] = __expf(s[nt][2] - mn1);
            s[nt][3] = __expf(s[nt][3] - mn1);
            rs0 += s[nt][0] + s[nt][1];
            rs1 += s[nt][2] + s[nt][3];
            // store P (tf32) to this warp's private Ps rows
            uint32_t* p0 = &Ps[(wid * 16 + gid    ) * PAD + nt * 8 + tig * 2];
            uint32_t* p1 = &Ps[(wid * 16 + gid + 8) * PAD + nt * 8 + tig * 2];
            p0[0] = f2tf(s[nt][0]); p0[1] = f2tf(s[nt][1]);
            p1[0] = f2tf(s[nt][2]); p1[1] = f2tf(s[nt][3]);
        }
        rs0 += __shfl_xor_sync(0xffffffffu, rs0, 1);
        rs0 += __shfl_xor_sync(0xffffffffu, rs0, 2);
        rs1 += __shfl_xor_sync(0xffffffffu, rs1, 1);
        rs1 += __shfl_xor_sync(0xffffffffu, rs1, 2);
        l0 = l0 * cr0 + rs0;
        l1 = l1 * cr1 + rs1;

        #pragma unroll
        for (int nt = 0; nt < 8; nt++) {
            o[nt][0] *= cr0; o[nt][1] *= cr0;
            o[nt][2] *= cr1; o[nt][3] *= cr1;
        }
        __syncwarp();   // Ps rows are warp-private: warp-local sync suffices

        // --- O += P V ---  (contraction over key; n = h)
        #pragma unroll
        for (int s8 = 0; s8 < 8; s8++) {
            uint32_t pa[4];
            const int pr = wid * 16 + gid;
            pa[0] = Ps[(pr    ) * PAD + s8 * 8 + tig    ];
            pa[1] = Ps[(pr + 8) * PAD + s8 * 8 + tig    ];
            pa[2] = Ps[(pr    ) * PAD + s8 * 8 + tig + 4];
            pa[3] = Ps[(pr + 8) * PAD + s8 * 8 + tig + 4];
            #pragma unroll
            for (int nt = 0; nt < 8; nt++) {
                uint32_t b0 = Vs[(s8 * 8 + tig    ) * PAD + nt * 8 + gid];
                uint32_t b1 = Vs[(s8 * 8 + tig + 4) * PAD + nt * 8 + gid];
                mma_tf32(o[nt], pa, b0, b1);
            }
        }
        __syncthreads();   // before next K/V overwrite
    }

    // --- final normalize + write ---
    const float inv0 = 1.0f / l0;
    const float inv1 = 1.0f / l1;
    float* orow0 = &outp[((size_t)b * Tt + qr0    ) * Hh];
    float* orow1 = &outp[((size_t)b * Tt + qr0 + 8) * Hh];
    #pragma unroll
    for (int nt = 0; nt < 8; nt++) {
        *(float2*)&orow0[nt * 8 + tig * 2] =
            make_float2(o[nt][0] * inv0, o[nt][1] * inv0);
        *(float2*)&orow1[nt * 8 + tig * 2] =
            make_float2(o[nt][2] * inv1, o[nt][3] * inv1);
    }
}

// ---------------------------------------------------------------------------
extern "C" void kernel_launch(void* const* d_in, const int* in_sizes, int n_in,
                              void* d_out, int out_size)
{
    const float* x    = (const float*)d_in[0];
    const float* bias = (const float*)d_in[1];
    const float* wk   = (const float*)d_in[2];
    const float* wq   = (const float*)d_in[3];
    const float* wv   = (const float*)d_in[4];
    float* out = (float*)d_out;

    dim3 g1(Bb * Tt / 64, 3);
    proj_kernel<<<g1, 128>>>(x, wk, wq, wv);

    const int smem = 3 * 64 * PAD * 4;   // 52224 B
    cudaFuncSetAttribute(attn_kernel,
                         cudaFuncAttributeMaxDynamicSharedMemorySize, smem);
    dim3 g2(Tt / 64, Bb);
    attn_kernel<<<g2, 128, smem>>>(bias, out);
}

// round 3
// speedup vs baseline: 2.5824x; 1.4976x over previous
#include <cuda_runtime.h>
#include <cuda_bf16.h>
#include <cstdint>

// Problem constants
#define Bb 4
#define Tt 4096
#define Cc 1024
#define Hh 64
#define KPAD 68    // K smem stride (words): gid-row loads conflict-free
#define VPAD 72    // V smem stride (words): tig-row loads conflict-free
#define WPAD 200   // W smem stride (words): tig-row loads conflict-free

// Scratch for projected q/k/v (4 MB each)
__device__ float g_q[Bb * Tt * Hh];
__device__ float g_k[Bb * Tt * Hh];
__device__ float g_v[Bb * Tt * Hh];

__device__ __forceinline__ uint32_t f2tf(float f) {
    uint32_t u; asm("cvt.rna.tf32.f32 %0, %1;" : "=r"(u) : "f"(f)); return u;
}

// D += A(16x8) * B(8x8) (row.col), tf32 in, f32 accum
__device__ __forceinline__ void mma_tf32(float* d, const uint32_t* a,
                                         uint32_t b0, uint32_t b1) {
    asm volatile(
        "mma.sync.aligned.m16n8k8.row.col.f32.tf32.tf32.f32 "
        "{%0,%1,%2,%3}, {%4,%5,%6,%7}, {%8,%9}, {%0,%1,%2,%3};"
        : "+f"(d[0]), "+f"(d[1]), "+f"(d[2]), "+f"(d[3])
        : "r"(a[0]), "r"(a[1]), "r"(a[2]), "r"(a[3]), "r"(b0), "r"(b1));
}

// ---------------------------------------------------------------------------
// Kernel 1: fused QKV projection via tf32 mma.
// M=16384, K=1024, N=3x64.  CTA: 128 threads (4 warps), 64-row M tile.
// X tile loaded once per k-chunk; all 3 weight tiles in one smem buffer.
// Each warp: m16 x (3x64) n, 24 n-tiles.
// ---------------------------------------------------------------------------
__global__ __launch_bounds__(128, 3) void proj_kernel(
    const float* __restrict__ x,
    const float* __restrict__ wk,
    const float* __restrict__ wq,
    const float* __restrict__ wv)
{
    extern __shared__ uint32_t smp[];
    uint32_t* Xs = smp;                 // [m][c] tf32, stride KPAD
    uint32_t* Ws = smp + 64 * KPAD;     // [c][z*64+h] tf32, stride WPAD

    const int m0 = blockIdx.x * 64;
    const int tid = threadIdx.x;
    const int wid = tid >> 5;
    const int lane = tid & 31;
    const int gid = lane >> 2;
    const int tig = lane & 3;
    const int lc = tid & 15;
    const int lr = tid >> 4;

    float o[24][4];
    #pragma unroll
    for (int nt = 0; nt < 24; nt++)
        #pragma unroll
        for (int j = 0; j < 4; j++) o[nt][j] = 0.f;

    for (int k0 = 0; k0 < Cc; k0 += 64) {
        #pragma unroll
        for (int p = 0; p < 8; p++) {
            const int row = p * 8 + lr;
            float4 xv = *(const float4*)&x[(size_t)(m0 + row) * Cc + k0 + lc * 4];
            uint32_t* xd = &Xs[row * KPAD + lc * 4];
            xd[0] = f2tf(xv.x); xd[1] = f2tf(xv.y); xd[2] = f2tf(xv.z); xd[3] = f2tf(xv.w);
        }
        #pragma unroll
        for (int z = 0; z < 3; z++) {
            const float* __restrict__ w = (z == 0) ? wk : ((z == 1) ? wq : wv);
            #pragma unroll
            for (int p = 0; p < 8; p++) {
                const int row = p * 8 + lr;
                float4 wv4 = *(const float4*)&w[(size_t)(k0 + row) * Hh + lc * 4];
                uint32_t* wd = &Ws[row * WPAD + z * 64 + lc * 4];
                wd[0] = f2tf(wv4.x); wd[1] = f2tf(wv4.y); wd[2] = f2tf(wv4.z); wd[3] = f2tf(wv4.w);
            }
        }
        __syncthreads();

        #pragma unroll
        for (int s8 = 0; s8 < 8; s8++) {
            uint32_t a[4];
            const int ar = wid * 16 + gid;
            a[0] = Xs[(ar    ) * KPAD + s8 * 8 + tig    ];
            a[1] = Xs[(ar + 8) * KPAD + s8 * 8 + tig    ];
            a[2] = Xs[(ar    ) * KPAD + s8 * 8 + tig + 4];
            a[3] = Xs[(ar + 8) * KPAD + s8 * 8 + tig + 4];
            #pragma unroll
            for (int nt = 0; nt < 24; nt++) {
                uint32_t b0 = Ws[(s8 * 8 + tig    ) * WPAD + nt * 8 + gid];
                uint32_t b1 = Ws[(s8 * 8 + tig + 4) * WPAD + nt * 8 + gid];
                mma_tf32(o[nt], a, b0, b1);
            }
        }
        __syncthreads();
    }

    const int mr = m0 + wid * 16 + gid;
    #pragma unroll
    for (int nt = 0; nt < 24; nt++) {
        const int z = nt >> 3;
        float* __restrict__ outp = (z == 0) ? g_k : ((z == 1) ? g_q : g_v);
        const float scale = (z == 1) ? 0.125f : 1.0f;
        const int hc = (nt & 7) * 8 + tig * 2;
        *(float2*)&outp[(size_t)(mr    ) * Hh + hc] =
            make_float2(o[nt][0] * scale, o[nt][1] * scale);
        *(float2*)&outp[(size_t)(mr + 8) * Hh + hc] =
            make_float2(o[nt][2] * scale, o[nt][3] * scale);
    }
}

// ---------------------------------------------------------------------------
// Kernel 2: causal flash attention, tf32 mma, P kept in registers.
// Grid (T/64, B), CTA = 128 threads (4 warps), BQ=64, BK=64.
// Q fragments register-resident; K/V in smem.  V rows are slot-permuted so
// the QK^T accumulator can be fed directly as the PV A-operand.
// ---------------------------------------------------------------------------
__global__ __launch_bounds__(128, 3) void attn_kernel(
    const float* __restrict__ bias,
    float* __restrict__ outp)
{
    extern __shared__ uint32_t smu[];
    uint32_t* Ks = smu;                 // [key][h] tf32, stride KPAD
    uint32_t* Vs = smu + 64 * KPAD;     // [slot][h] tf32, stride VPAD (rows permuted)

    const int b  = blockIdx.y;
    const int qt = (gridDim.x - 1) - blockIdx.x;   // longest q-tiles first
    const int q0 = qt * 64;
    const int tid = threadIdx.x;
    const int wid = tid >> 5;
    const int lane = tid & 31;
    const int gid = lane >> 2;
    const int tig = lane & 3;
    const int lc = tid & 15;
    const int lr = tid >> 4;

    const float* __restrict__ qbase = g_q + (size_t)b * Tt * Hh;
    const float* __restrict__ kbase = g_k + (size_t)b * Tt * Hh;
    const float* __restrict__ vbase = g_v + (size_t)b * Tt * Hh;

    // Q fragments: this warp's 16 rows x H=64 (8 k-steps), register-resident.
    const int qr0 = q0 + wid * 16 + gid;
    uint32_t qa[8][4];
    #pragma unroll
    for (int s8 = 0; s8 < 8; s8++) {
        qa[s8][0] = f2tf(qbase[(size_t)(qr0    ) * Hh + s8 * 8 + tig    ]);
        qa[s8][1] = f2tf(qbase[(size_t)(qr0 + 8) * Hh + s8 * 8 + tig    ]);
        qa[s8][2] = f2tf(qbase[(size_t)(qr0    ) * Hh + s8 * 8 + tig + 4]);
        qa[s8][3] = f2tf(qbase[(size_t)(qr0 + 8) * Hh + s8 * 8 + tig + 4]);
    }

    float o[8][4];
    #pragma unroll
    for (int nt = 0; nt < 8; nt++)
        #pragma unroll
        for (int j = 0; j < 4; j++) o[nt][j] = 0.f;
    float m0r = -1e30f, m1r = -1e30f, l0 = 0.f, l1 = 0.f;

    for (int t = 0; t <= qt; t++) {
        const int k0 = t * 64;

        // Load K (plain) and V (slot-permuted rows) tiles -> tf32 smem
        #pragma unroll
        for (int p = 0; p < 8; p++) {
            const int row = p * 8 + lr;
            const int r7 = row & 7;
            const int srow = (row & ~7) | ((r7 & 1) ? ((r7 >> 1) + 4) : (r7 >> 1));
            float4 kv = *(const float4*)&kbase[(size_t)(k0 + row) * Hh + lc * 4];
            float4 vv = *(const float4*)&vbase[(size_t)(k0 + row) * Hh + lc * 4];
            uint32_t* kd = &Ks[row * KPAD + lc * 4];
            kd[0] = f2tf(kv.x); kd[1] = f2tf(kv.y); kd[2] = f2tf(kv.z); kd[3] = f2tf(kv.w);
            uint32_t* vd = &Vs[srow * VPAD + lc * 4];
            vd[0] = f2tf(vv.x); vd[1] = f2tf(vv.y); vd[2] = f2tf(vv.z); vd[3] = f2tf(vv.w);
        }
        __syncthreads();

        // --- S = Q K^T ---
        float s[8][4];
        #pragma unroll
        for (int nt = 0; nt < 8; nt++) {
            #pragma unroll
            for (int j = 0; j < 4; j++) s[nt][j] = 0.f;
            const uint32_t* krow = &Ks[(nt * 8 + gid) * KPAD];
            #pragma unroll
            for (int s8 = 0; s8 < 8; s8++) {
                uint32_t b0 = krow[s8 * 8 + tig    ];
                uint32_t b1 = krow[s8 * 8 + tig + 4];
                mma_tf32(s[nt], qa[s8], b0, b1);
            }
        }

        // --- bias + causal mask ---
        const bool diag = (t == qt);
        #pragma unroll
        for (int nt = 0; nt < 8; nt++) {
            const int c0 = k0 + nt * 8 + tig * 2;
            float2 bz0 = *(const float2*)&bias[(size_t)(qr0    ) * Tt + c0];
            float2 bz1 = *(const float2*)&bias[(size_t)(qr0 + 8) * Tt + c0];
            s[nt][0] += bz0.x; s[nt][1] += bz0.y;
            s[nt][2] += bz1.x; s[nt][3] += bz1.y;
            if (diag) {
                if (c0     > qr0    ) s[nt][0] = -1e30f;
                if (c0 + 1 > qr0    ) s[nt][1] = -1e30f;
                if (c0     > qr0 + 8) s[nt][2] = -1e30f;
                if (c0 + 1 > qr0 + 8) s[nt][3] = -1e30f;
            }
        }

        // --- online softmax (rows qr0, qr0+8; 4 lanes per row) ---
        float mx0 = -1e30f, mx1 = -1e30f;
        #pragma unroll
        for (int nt = 0; nt < 8; nt++) {
            mx0 = fmaxf(mx0, fmaxf(s[nt][0], s[nt][1]));
            mx1 = fmaxf(mx1, fmaxf(s[nt][2], s[nt][3]));
        }
        mx0 = fmaxf(mx0, __shfl_xor_sync(0xffffffffu, mx0, 1));
        mx0 = fmaxf(mx0, __shfl_xor_sync(0xffffffffu, mx0, 2));
        mx1 = fmaxf(mx1, __shfl_xor_sync(0xffffffffu, mx1, 1));
        mx1 = fmaxf(mx1, __shfl_xor_sync(0xffffffffu, mx1, 2));

        const float mn0 = fmaxf(m0r, mx0);
        const float mn1 = fmaxf(m1r, mx1);
        const float cr0 = __expf(m0r - mn0);
        const float cr1 = __expf(m1r - mn1);
        m0r = mn0; m1r = mn1;

        float rs0 = 0.f, rs1 = 0.f;
        #pragma unroll
        for (int nt = 0; nt < 8; nt++) {
            s[nt][0] = __expf(s[nt][0] - mn0);
            s[nt][1] = __expf(s[nt][1] - mn0);
            s[nt][2] = __expf(s[nt][2] - mn1);
            s[nt][3] = __expf(s[nt][3] - mn1);
            rs0 += s[nt][0] + s[nt][1];
            rs1 += s[nt][2] + s[nt][3];
        }
        rs0 += __shfl_xor_sync(0xffffffffu, rs0, 1);
        rs0 += __shfl_xor_sync(0xffffffffu, rs0, 2);
        rs1 += __shfl_xor_sync(0xffffffffu, rs1, 1);
        rs1 += __shfl_xor_sync(0xffffffffu, rs1, 2);
        l0 = l0 * cr0 + rs0;
        l1 = l1 * cr1 + rs1;

        #pragma unroll
        for (int nt = 0; nt < 8; nt++) {
            o[nt][0] *= cr0; o[nt][1] *= cr0;
            o[nt][2] *= cr1; o[nt][3] *= cr1;
        }

        // --- O += P V ---  P comes straight from the accumulator:
        // A slot j<4 holds key 2j, slot j>=4 holds key 2j-7; V rows were
        // stored permuted to match, so plain mma semantics give P·V.
        #pragma unroll
        for (int c = 0; c < 8; c++) {
            uint32_t pa[4];
            pa[0] = f2tf(s[c][0]);   // (gid,   key 2tig)
            pa[1] = f2tf(s[c][2]);   // (gid+8, key 2tig)
            pa[2] = f2tf(s[c][1]);   // (gid,   key 2tig+1)
            pa[3] = f2tf(s[c][3]);   // (gid+8, key 2tig+1)
            const uint32_t* vrow0 = &Vs[(c * 8 + tig    ) * VPAD];
            const uint32_t* vrow1 = &Vs[(c * 8 + tig + 4) * VPAD];
            #pragma unroll
            for (int nt = 0; nt < 8; nt++) {
                uint32_t b0 = vrow0[nt * 8 + gid];
                uint32_t b1 = vrow1[nt * 8 + gid];
                mma_tf32(o[nt], pa, b0, b1);
            }
        }
        __syncthreads();   // before next K/V overwrite
    }

    // --- final normalize + write ---
    const float inv0 = 1.0f / l0;
    const float inv1 = 1.0f / l1;
    float* orow0 = &outp[((size_t)b * Tt + qr0    ) * Hh];
    float* orow1 = &outp[((size_t)b * Tt + qr0 + 8) * Hh];
    #pragma unroll
    for (int nt = 0; nt < 8; nt++) {
        *(float2*)&orow0[nt * 8 + tig * 2] =
            make_float2(o[nt][0] * inv0, o[nt][1] * inv0);
        *(float2*)&orow1[nt * 8 + tig * 2] =
            make_float2(o[nt][2] * inv1, o[nt][3] * inv1);
    }
}

// ---------------------------------------------------------------------------
extern "C" void kernel_launch(void* const* d_in, const int* in_sizes, int n_in,
                              void* d_out, int out_size)
{
    const float* x    = (const float*)d_in[0];
    const float* bias = (const float*)d_in[1];
    const float* wk   = (const float*)d_in[2];
    const float* wq   = (const float*)d_in[3];
    const float* wv   = (const float*)d_in[4];
    float* out = (float*)d_out;

    const int psmem = (64 * KPAD + 64 * WPAD) * 4;   // 68608 B
    cudaFuncSetAttribute(proj_kernel,
                         cudaFuncAttributeMaxDynamicSharedMemorySize, psmem);
    proj_kernel<<<Bb * Tt / 64, 128, psmem>>>(x, wk, wq, wv);

    const int asmem = (64 * KPAD + 64 * VPAD) * 4;   // 35840 B
    cudaFuncSetAttribute(attn_kernel,
                         cudaFuncAttributeMaxDynamicSharedMemorySize, asmem);
    dim3 g2(Tt / 64, Bb);
    attn_kernel<<<g2, 128, asmem>>>(bias, out);
}

// round 5
// speedup vs baseline: 3.4976x; 1.3544x over previous
#include <cuda_runtime.h>
#include <cuda_bf16.h>
#include <cstdint>

// Problem constants
#define Bb 4
#define Tt 4096
#define Cc 1024
#define Hh 64
#define KPAD 68    // K/X smem stride (words)
#define VPAD 72    // V smem stride (words)
#define WPAD 200   // W smem stride (words)
#define NCHUNK 16  // key-tiles per split chunk (1024 keys)

// Scratch for projected q/k/v (4 MB each)
__device__ float g_q[Bb * Tt * Hh];
__device__ float g_k[Bb * Tt * Hh];
__device__ float g_v[Bb * Tt * Hh];

// Split-K partials: slot = ((b*64+qt)*4 + ci)
__device__ float  g_pO[Bb * 64 * 4][64][Hh];     // unnormalized O
__device__ float2 g_pml[Bb * 64 * 4][64];        // (m, l) per row

__device__ __forceinline__ uint32_t f2tf(float f) {
    uint32_t u; asm("cvt.rna.tf32.f32 %0, %1;" : "=r"(u) : "f"(f)); return u;
}

__device__ __forceinline__ void mma_tf32(float* d, const uint32_t* a,
                                         uint32_t b0, uint32_t b1) {
    asm volatile(
        "mma.sync.aligned.m16n8k8.row.col.f32.tf32.tf32.f32 "
        "{%0,%1,%2,%3}, {%4,%5,%6,%7}, {%8,%9}, {%0,%1,%2,%3};"
        : "+f"(d[0]), "+f"(d[1]), "+f"(d[2]), "+f"(d[3])
        : "r"(a[0]), "r"(a[1]), "r"(a[2]), "r"(a[3]), "r"(b0), "r"(b1));
}

// ---------------------------------------------------------------------------
// Kernel 1: fused QKV projection via tf32 mma.
// CTA: 128 threads (4 warps), 64-row M tile, N = 3*64 = 192 (24 n-tiles).
// Warp tiling: each warp covers ALL 4 m-row-blocks x 6 n-tiles
// -> W fragment smem reads cut 4x vs per-warp-row tiling.
// ---------------------------------------------------------------------------
__global__ __launch_bounds__(128, 3) void proj_kernel(
    const float* __restrict__ x,
    const float* __restrict__ wk,
    const float* __restrict__ wq,
    const float* __restrict__ wv)
{
    extern __shared__ uint32_t smp[];
    uint32_t* Xs = smp;                 // [m][c] tf32, stride KPAD
    uint32_t* Ws = smp + 64 * KPAD;     // [c][z*64+h] tf32, stride WPAD

    const int m0 = blockIdx.x * 64;
    const int tid = threadIdx.x;
    const int wid = tid >> 5;
    const int lane = tid & 31;
    const int gid = lane >> 2;
    const int tig = lane & 3;
    const int lc = tid & 15;
    const int lr = tid >> 4;

    float o[6][4][4];   // [nt][row-block][frag]
    #pragma unroll
    for (int nt = 0; nt < 6; nt++)
        #pragma unroll
        for (int rb = 0; rb < 4; rb++)
            #pragma unroll
            for (int j = 0; j < 4; j++) o[nt][rb][j] = 0.f;

    for (int k0 = 0; k0 < Cc; k0 += 64) {
        #pragma unroll
        for (int p = 0; p < 8; p++) {
            const int row = p * 8 + lr;
            float4 xv = *(const float4*)&x[(size_t)(m0 + row) * Cc + k0 + lc * 4];
            uint32_t* xd = &Xs[row * KPAD + lc * 4];
            xd[0] = f2tf(xv.x); xd[1] = f2tf(xv.y); xd[2] = f2tf(xv.z); xd[3] = f2tf(xv.w);
        }
        #pragma unroll
        for (int z = 0; z < 3; z++) {
            const float* __restrict__ w = (z == 0) ? wk : ((z == 1) ? wq : wv);
            #pragma unroll
            for (int p = 0; p < 8; p++) {
                const int row = p * 8 + lr;
                float4 wv4 = *(const float4*)&w[(size_t)(k0 + row) * Hh + lc * 4];
                uint32_t* wd = &Ws[row * WPAD + z * 64 + lc * 4];
                wd[0] = f2tf(wv4.x); wd[1] = f2tf(wv4.y); wd[2] = f2tf(wv4.z); wd[3] = f2tf(wv4.w);
            }
        }
        __syncthreads();

        #pragma unroll
        for (int s8 = 0; s8 < 8; s8++) {
            uint32_t a[4][4];
            #pragma unroll
            for (int rb = 0; rb < 4; rb++) {
                const int ar = rb * 16 + gid;
                a[rb][0] = Xs[(ar    ) * KPAD + s8 * 8 + tig    ];
                a[rb][1] = Xs[(ar + 8) * KPAD + s8 * 8 + tig    ];
                a[rb][2] = Xs[(ar    ) * KPAD + s8 * 8 + tig + 4];
                a[rb][3] = Xs[(ar + 8) * KPAD + s8 * 8 + tig + 4];
            }
            #pragma unroll
            for (int nt = 0; nt < 6; nt++) {
                const int ntp = wid * 6 + nt;
                uint32_t b0 = Ws[(s8 * 8 + tig    ) * WPAD + ntp * 8 + gid];
                uint32_t b1 = Ws[(s8 * 8 + tig + 4) * WPAD + ntp * 8 + gid];
                #pragma unroll
                for (int rb = 0; rb < 4; rb++)
                    mma_tf32(o[nt][rb], a[rb], b0, b1);
            }
        }
        __syncthreads();
    }

    #pragma unroll
    for (int nt = 0; nt < 6; nt++) {
        const int ntp = wid * 6 + nt;
        const int z = ntp >> 3;
        float* __restrict__ outp = (z == 0) ? g_k : ((z == 1) ? g_q : g_v);
        const float scale = (z == 1) ? 0.125f : 1.0f;
        const int hc = (ntp & 7) * 8 + tig * 2;
        #pragma unroll
        for (int rb = 0; rb < 4; rb++) {
            const int mr = m0 + rb * 16 + gid;
            *(float2*)&outp[(size_t)(mr    ) * Hh + hc] =
                make_float2(o[nt][rb][0] * scale, o[nt][rb][1] * scale);
            *(float2*)&outp[(size_t)(mr + 8) * Hh + hc] =
                make_float2(o[nt][rb][2] * scale, o[nt][rb][3] * scale);
        }
    }
}

// ---------------------------------------------------------------------------
// Kernel 2: split-K causal flash attention, tf32 mma, P in registers.
// 640 work units: (b, qt, chunk of <=16 key-tiles).  Single-chunk q-tiles
// write out directly; multi-chunk units write (O, m, l) partials.
// ---------------------------------------------------------------------------
__global__ __launch_bounds__(128, 3) void attn_kernel(
    const float* __restrict__ bias,
    float* __restrict__ outp)
{
    extern __shared__ uint32_t smu[];
    uint32_t* Ks = smu;                 // [key][h] tf32, stride KPAD
    uint32_t* Vs = smu + 64 * KPAD;     // [slot][h] tf32, stride VPAD (permuted rows)

    // Unit decode: bx -> (b, u) with u descending work.
    const int b = blockIdx.x & 3;
    const int v = blockIdx.x >> 2;      // 0..159
    const int u = 159 - v;
    int qt, ci, nch;
    if (u < 16)      { qt = u;                 ci = 0;            nch = 1; }
    else if (u < 48) { int j = u - 16; qt = 16 + (j >> 1); ci = j & 1; nch = 2; }
    else if (u < 96) { int j = u - 48; qt = 32 + j / 3;    ci = j % 3; nch = 3; }
    else             { int j = u - 96; qt = 48 + (j >> 2); ci = j & 3; nch = 4; }

    const int q0 = qt * 64;
    const int t0 = ci * NCHUNK;
    const int t1 = min(t0 + NCHUNK, qt + 1);

    const int tid = threadIdx.x;
    const int wid = tid >> 5;
    const int lane = tid & 31;
    const int gid = lane >> 2;
    const int tig = lane & 3;
    const int lc = tid & 15;
    const int lr = tid >> 4;

    const float* __restrict__ qbase = g_q + (size_t)b * Tt * Hh;
    const float* __restrict__ kbase = g_k + (size_t)b * Tt * Hh;
    const float* __restrict__ vbase = g_v + (size_t)b * Tt * Hh;

    const int qr0 = q0 + wid * 16 + gid;
    uint32_t qa[8][4];
    #pragma unroll
    for (int s8 = 0; s8 < 8; s8++) {
        qa[s8][0] = f2tf(qbase[(size_t)(qr0    ) * Hh + s8 * 8 + tig    ]);
        qa[s8][1] = f2tf(qbase[(size_t)(qr0 + 8) * Hh + s8 * 8 + tig    ]);
        qa[s8][2] = f2tf(qbase[(size_t)(qr0    ) * Hh + s8 * 8 + tig + 4]);
        qa[s8][3] = f2tf(qbase[(size_t)(qr0 + 8) * Hh + s8 * 8 + tig + 4]);
    }

    float o[8][4];
    #pragma unroll
    for (int nt = 0; nt < 8; nt++)
        #pragma unroll
        for (int j = 0; j < 4; j++) o[nt][j] = 0.f;
    float m0r = -1e30f, m1r = -1e30f, l0 = 0.f, l1 = 0.f;

    for (int t = t0; t < t1; t++) {
        const int k0 = t * 64;

        #pragma unroll
        for (int p = 0; p < 8; p++) {
            const int row = p * 8 + lr;
            const int r7 = row & 7;
            const int srow = (row & ~7) | ((r7 & 1) ? ((r7 >> 1) + 4) : (r7 >> 1));
            float4 kv = *(const float4*)&kbase[(size_t)(k0 + row) * Hh + lc * 4];
            float4 vv = *(const float4*)&vbase[(size_t)(k0 + row) * Hh + lc * 4];
            uint32_t* kd = &Ks[row * KPAD + lc * 4];
            kd[0] = f2tf(kv.x); kd[1] = f2tf(kv.y); kd[2] = f2tf(kv.z); kd[3] = f2tf(kv.w);
            uint32_t* vd = &Vs[srow * VPAD + lc * 4];
            vd[0] = f2tf(vv.x); vd[1] = f2tf(vv.y); vd[2] = f2tf(vv.z); vd[3] = f2tf(vv.w);
        }
        __syncthreads();

        // --- S = Q K^T ---
        float s[8][4];
        #pragma unroll
        for (int nt = 0; nt < 8; nt++) {
            #pragma unroll
            for (int j = 0; j < 4; j++) s[nt][j] = 0.f;
            const uint32_t* krow = &Ks[(nt * 8 + gid) * KPAD];
            #pragma unroll
            for (int s8 = 0; s8 < 8; s8++) {
                uint32_t b0 = krow[s8 * 8 + tig    ];
                uint32_t b1 = krow[s8 * 8 + tig + 4];
                mma_tf32(s[nt], qa[s8], b0, b1);
            }
        }

        // --- bias + causal mask ---
        const bool diag = (t == qt);
        #pragma unroll
        for (int nt = 0; nt < 8; nt++) {
            const int c0 = k0 + nt * 8 + tig * 2;
            float2 bz0 = *(const float2*)&bias[(size_t)(qr0    ) * Tt + c0];
            float2 bz1 = *(const float2*)&bias[(size_t)(qr0 + 8) * Tt + c0];
            s[nt][0] += bz0.x; s[nt][1] += bz0.y;
            s[nt][2] += bz1.x; s[nt][3] += bz1.y;
            if (diag) {
                if (c0     > qr0    ) s[nt][0] = -1e30f;
                if (c0 + 1 > qr0    ) s[nt][1] = -1e30f;
                if (c0     > qr0 + 8) s[nt][2] = -1e30f;
                if (c0 + 1 > qr0 + 8) s[nt][3] = -1e30f;
            }
        }

        // --- online softmax ---
        float mx0 = -1e30f, mx1 = -1e30f;
        #pragma unroll
        for (int nt = 0; nt < 8; nt++) {
            mx0 = fmaxf(mx0, fmaxf(s[nt][0], s[nt][1]));
            mx1 = fmaxf(mx1, fmaxf(s[nt][2], s[nt][3]));
        }
        mx0 = fmaxf(mx0, __shfl_xor_sync(0xffffffffu, mx0, 1));
        mx0 = fmaxf(mx0, __shfl_xor_sync(0xffffffffu, mx0, 2));
        mx1 = fmaxf(mx1, __shfl_xor_sync(0xffffffffu, mx1, 1));
        mx1 = fmaxf(mx1, __shfl_xor_sync(0xffffffffu, mx1, 2));

        const float mn0 = fmaxf(m0r, mx0);
        const float mn1 = fmaxf(m1r, mx1);
        const float cr0 = __expf(m0r - mn0);
        const float cr1 = __expf(m1r - mn1);
        m0r = mn0; m1r = mn1;

        float rs0 = 0.f, rs1 = 0.f;
        #pragma unroll
        for (int nt = 0; nt < 8; nt++) {
            s[nt][0] = __expf(s[nt][0] - mn0);
            s[nt][1] = __expf(s[nt][1] - mn0);
            s[nt][2] = __expf(s[nt][2] - mn1);
            s[nt][3] = __expf(s[nt][3] - mn1);
            rs0 += s[nt][0] + s[nt][1];
            rs1 += s[nt][2] + s[nt][3];
        }
        rs0 += __shfl_xor_sync(0xffffffffu, rs0, 1);
        rs0 += __shfl_xor_sync(0xffffffffu, rs0, 2);
        rs1 += __shfl_xor_sync(0xffffffffu, rs1, 1);
        rs1 += __shfl_xor_sync(0xffffffffu, rs1, 2);
        l0 = l0 * cr0 + rs0;
        l1 = l1 * cr1 + rs1;

        #pragma unroll
        for (int nt = 0; nt < 8; nt++) {
            o[nt][0] *= cr0; o[nt][1] *= cr0;
            o[nt][2] *= cr1; o[nt][3] *= cr1;
        }

        // --- O += P V (P straight from accumulator; V rows slot-permuted) ---
        #pragma unroll
        for (int c = 0; c < 8; c++) {
            uint32_t pa[4];
            pa[0] = f2tf(s[c][0]);
            pa[1] = f2tf(s[c][2]);
            pa[2] = f2tf(s[c][1]);
            pa[3] = f2tf(s[c][3]);
            const uint32_t* vrow0 = &Vs[(c * 8 + tig    ) * VPAD];
            const uint32_t* vrow1 = &Vs[(c * 8 + tig + 4) * VPAD];
            #pragma unroll
            for (int nt = 0; nt < 8; nt++) {
                uint32_t b0 = vrow0[nt * 8 + gid];
                uint32_t b1 = vrow1[nt * 8 + gid];
                mma_tf32(o[nt], pa, b0, b1);
            }
        }
        __syncthreads();
    }

    if (nch == 1) {
        // Direct write
        const float inv0 = 1.0f / l0;
        const float inv1 = 1.0f / l1;
        float* orow0 = &outp[((size_t)b * Tt + qr0    ) * Hh];
        float* orow1 = &outp[((size_t)b * Tt + qr0 + 8) * Hh];
        #pragma unroll
        for (int nt = 0; nt < 8; nt++) {
            *(float2*)&orow0[nt * 8 + tig * 2] =
                make_float2(o[nt][0] * inv0, o[nt][1] * inv0);
            *(float2*)&orow1[nt * 8 + tig * 2] =
                make_float2(o[nt][2] * inv1, o[nt][3] * inv1);
        }
    } else {
        // Partial write: unnormalized O plus (m, l)
        const int slot = (b * 64 + qt) * 4 + ci;
        const int r0 = wid * 16 + gid;
        float* prow0 = g_pO[slot][r0];
        float* prow1 = g_pO[slot][r0 + 8];
        #pragma unroll
        for (int nt = 0; nt < 8; nt++) {
            *(float2*)&prow0[nt * 8 + tig * 2] = make_float2(o[nt][0], o[nt][1]);
            *(float2*)&prow1[nt * 8 + tig * 2] = make_float2(o[nt][2], o[nt][3]);
        }
        if (tig == 0) {
            g_pml[slot][r0    ] = make_float2(m0r, l0);
            g_pml[slot][r0 + 8] = make_float2(m1r, l1);
        }
    }
}

// ---------------------------------------------------------------------------
// Kernel 3: merge split-K partials for qt >= 16.
// Grid: 4*48 CTAs, 256 threads.  Thread: (row = tid>>2, h-seg = tid&3).
// ---------------------------------------------------------------------------
__global__ __launch_bounds__(256) void reduce_kernel(float* __restrict__ outp)
{
    const int b  = blockIdx.x / 48;
    const int qt = 16 + blockIdx.x % 48;
    const int nch = (qt >> 4) + 1;
    const int row = threadIdx.x >> 2;
    const int seg = threadIdx.x & 3;
    const int slot0 = (b * 64 + qt) * 4;

    float m[4], w[4];
    float M = -1e30f;
    #pragma unroll
    for (int i = 0; i < 4; i++) {
        if (i < nch) { m[i] = g_pml[slot0 + i][row].x; M = fmaxf(M, m[i]); }
    }
    float L = 0.f;
    #pragma unroll
    for (int i = 0; i < 4; i++) {
        if (i < nch) {
            w[i] = __expf(m[i] - M);
            L += w[i] * g_pml[slot0 + i][row].y;
        }
    }
    const float inv = 1.0f / L;

    float* orow = &outp[((size_t)b * Tt + qt * 64 + row) * Hh + seg * 16];
    #pragma unroll
    for (int g4 = 0; g4 < 4; g4++) {
        float4 acc = make_float4(0.f, 0.f, 0.f, 0.f);
        #pragma unroll
        for (int i = 0; i < 4; i++) {
            if (i < nch) {
                float4 pv = *(const float4*)&g_pO[slot0 + i][row][seg * 16 + g4 * 4];
                acc.x += w[i] * pv.x; acc.y += w[i] * pv.y;
                acc.z += w[i] * pv.z; acc.w += w[i] * pv.w;
            }
        }
        acc.x *= inv; acc.y *= inv; acc.z *= inv; acc.w *= inv;
        *(float4*)&orow[g4 * 4] = acc;
    }
}

// ---------------------------------------------------------------------------
extern "C" void kernel_launch(void* const* d_in, const int* in_sizes, int n_in,
                              void* d_out, int out_size)
{
    const float* x    = (const float*)d_in[0];
    const float* bias = (const float*)d_in[1];
    const float* wk   = (const float*)d_in[2];
    const float* wq   = (const float*)d_in[3];
    const float* wv   = (const float*)d_in[4];
    float* out = (float*)d_out;

    const int psmem = (64 * KPAD + 64 * WPAD) * 4;   // 68608 B
    cudaFuncSetAttribute(proj_kernel,
                         cudaFuncAttributeMaxDynamicSharedMemorySize, psmem);
    proj_kernel<<<Bb * Tt / 64, 128, psmem>>>(x, wk, wq, wv);

    const int asmem = (64 * KPAD + 64 * VPAD) * 4;   // 35840 B
    cudaFuncSetAttribute(attn_kernel,
                         cudaFuncAttributeMaxDynamicSharedMemorySize, asmem);
    attn_kernel<<<640, 128, asmem>>>(bias, out);

    reduce_kernel<<<Bb * 48, 256>>>(out);
}